// round 13
// baseline (speedup 1.0000x reference)
#include <cuda_runtime.h>
#include <cuda_bf16.h>
#include <math.h>
#include <stdint.h>

#define N_NODES 8192
#define KSEL 32
#define ROWS_PER_CTA 64
#define CAP 320
#define TRIGGER 192

__device__ float g_Af[N_NODES * 128];                 // [v1 | -v2] fp32
__device__ float g_Bf[N_NODES * 128];                 // [v2 |  v1] fp32
__device__ __nv_bfloat16 g_Abf[N_NODES * 128];        // hi(A)
__device__ __nv_bfloat16 g_Bbf[N_NODES * 128];        // hi(B)

__device__ __forceinline__ uint32_t smem_u32(const void* p) {
    uint32_t a;
    asm("{ .reg .u64 t; cvta.to.shared.u64 t, %1; cvt.u32.u64 %0, t; }" : "=r"(a) : "l"(p));
    return a;
}
__device__ __forceinline__ uint32_t sw128(uint32_t byte) {
    return byte ^ ((byte >> 3) & 0x70);
}
__device__ __forceinline__ void ldmatrix_x4(uint32_t& r0, uint32_t& r1,
                                            uint32_t& r2, uint32_t& r3, uint32_t addr) {
    asm volatile("ldmatrix.sync.aligned.m8n8.x4.shared.b16 {%0,%1,%2,%3}, [%4];"
                 : "=r"(r0), "=r"(r1), "=r"(r2), "=r"(r3) : "r"(addr));
}
__device__ __forceinline__ void mma_bf16(float* c, const uint32_t* a, uint32_t b0, uint32_t b1) {
    asm volatile("mma.sync.aligned.m16n8k16.row.col.f32.bf16.bf16.f32 "
                 "{%0,%1,%2,%3}, {%4,%5,%6,%7}, {%8,%9}, {%0,%1,%2,%3};"
                 : "+f"(c[0]), "+f"(c[1]), "+f"(c[2]), "+f"(c[3])
                 : "r"(a[0]), "r"(a[1]), "r"(a[2]), "r"(a[3]), "r"(b0), "r"(b1));
}
__device__ __forceinline__ void cp_async16(uint32_t dst, const void* src) {
    asm volatile("cp.async.cg.shared.global [%0], [%1], 16;" :: "r"(dst), "l"(src) : "memory");
}
__device__ __forceinline__ void cp_commit() {
    asm volatile("cp.async.commit_group;" ::: "memory");
}
#define CP_WAIT(N) asm volatile("cp.async.wait_group %0;" :: "n"(N) : "memory")

// ---------------------------------------------------------------------------
// Kernel 1: prep — hi-only bf16 pack (unchanged)
// ---------------------------------------------------------------------------
__global__ void __launch_bounds__(128) prep_kernel(
    const float* __restrict__ emb,
    const float* __restrict__ W1, const float* __restrict__ b1,
    const float* __restrict__ W2, const float* __restrict__ b2)
{
    __shared__ float sW[2][64][65];
    __shared__ float sb[2][64];
    __shared__ float semb[16][64];

    const int tid = threadIdx.x;
    for (int i = tid; i < 64 * 64; i += 128) {
        int r = i >> 6, k = i & 63;
        sW[0][r][k] = W1[i];
        sW[1][r][k] = W2[i];
    }
    if (tid < 64) { sb[0][tid] = b1[tid]; sb[1][tid] = b2[tid]; }

    const int nodeBase = blockIdx.x * 16;
    for (int i = tid; i < 16 * 64; i += 128)
        semb[i >> 6][i & 63] = emb[(size_t)(nodeBase + (i >> 6)) * 64 + (i & 63)];
    __syncthreads();

    const int h = tid >> 6;
    const int r = tid & 63;
    for (int n = 0; n < 16; n++) {
        float acc = sb[h][r];
#pragma unroll
        for (int k = 0; k < 64; k++)
            acc = fmaf(semb[n][k], sW[h][r][k], acc);
        float v = 0.5f * acc * (1.0f + erff(acc * 0.70710678118654752f));
        const int node = nodeBase + n;

        if (h == 0) {
            g_Af[node * 128 + r]      = v;
            g_Bf[node * 128 + 64 + r] = v;
            __nv_bfloat16 hi = __float2bfloat16_rn(v);
            g_Abf[node * 128 + r]      = hi;
            g_Bbf[node * 128 + 64 + r] = hi;
        } else {
            float av = -v;
            g_Af[node * 128 + 64 + r] = av;
            g_Bf[node * 128 + r]      = v;
            g_Abf[node * 128 + 64 + r] = __float2bfloat16_rn(av);
            g_Bbf[node * 128 + r]      = __float2bfloat16_rn(v);
        }
    }
}

// ---------------------------------------------------------------------------
// Fused kernel: R10 geometry (128 CTAs x 512 thr, 64-row strips, 256-col
// tiles, cp.async pipeline). Changes: CAP 320 / trigger 192, and 4-lane
// warp-aggregated candidate appends (1 atomic per row-group).
// ---------------------------------------------------------------------------
#define OFF_A    0            // 2 chunks x 8KB = 16KB
#define OFF_B0   16384        // 32KB
#define OFF_B1   49152        // 32KB
#define OFF_CS   81920        // 64 * 320 * 4 = 81920
#define OFF_CJ   163840       // 64 * 320 * 2 = 40960
#define OFF_THR  204800
#define OFF_CNT  205056
#define SMEM_FUSED 205312

__global__ void __launch_bounds__(512) fused_kernel(
    const float* __restrict__ noise, float* __restrict__ out)
{
    extern __shared__ char smem[];
    const uint32_t sbase = smem_u32(smem);
    float*    cs  = (float*)(smem + OFF_CS);
    uint16_t* cj  = (uint16_t*)(smem + OFF_CJ);
    float*    thr = (float*)(smem + OFF_THR);
    int*      cnt = (int*)(smem + OFF_CNT);

    const int tid = threadIdx.x;
    const int lane = tid & 31;
    const int warp = tid >> 5;
    const int warpN = warp & 7;
    const int warpM = warp >> 3;
    const int rowBase = blockIdx.x * ROWS_PER_CTA;

    // zero output slab
    {
        float4* o4 = (float4*)(out + (size_t)rowBase * N_NODES);
        const float4 z = make_float4(0.f, 0.f, 0.f, 0.f);
        for (int i = tid; i < ROWS_PER_CTA * N_NODES / 4; i += 512) o4[i] = z;
    }
    if (tid < 64) { thr[tid] = -1.0f; cnt[tid] = 0; }

    // load A strip: 64 rows x 256B, 2 chunks of 8KB, SW128
    {
        const char* gA = (const char*)g_Abf;
        for (int idx = tid; idx < 1024; idx += 512) {
            int row = idx >> 4, rem = idx & 15;
            int c = rem >> 3, q = rem & 7;
            uint4 v = *(const uint4*)(gA + (size_t)(rowBase + row) * 256 + c * 128 + q * 16);
            *(uint4*)(smem + OFF_A + c * 8192 + sw128(row * 128 + q * 16)) = v;
        }
    }

    const int laneRow = lane & 15;
    const int laneK = lane >> 4;
    const int rowB = tid >> 3;
    const int qB = tid & 7;
    uint32_t stB[4];
#pragma unroll
    for (int r = 0; r < 4; r++)
        stB[r] = sw128((rowB + r * 64) * 128 + qB * 16);

    const char* gB = (const char*)g_Bbf;
    const int lrBase = warpM * 32 + (lane >> 2);

    auto issueB = [&](int g) {
        const uint32_t dstBase = sbase + ((g & 1) ? OFF_B1 : OFF_B0);
        const int tt = g >> 1, cc = g & 1;
        const char* src = gB + (size_t)(tt * 256 + rowB) * 256 + cc * 128 + qB * 16;
#pragma unroll
        for (int r = 0; r < 4; r++)
            cp_async16(dstBase + stB[r], src + (size_t)r * 64 * 256);
        cp_commit();
    };

    issueB(0);

    for (int t = 0; t < 32; t++) {
        const int colBase = t * 256;

        float acc[2][4][4];
#pragma unroll
        for (int mi = 0; mi < 2; mi++)
#pragma unroll
            for (int n8 = 0; n8 < 4; n8++)
#pragma unroll
                for (int q = 0; q < 4; q++) acc[mi][n8][q] = 0.0f;

#pragma unroll
        for (int c = 0; c < 2; c++) {
            const int g = t * 2 + c;
            CP_WAIT(0);
            __syncthreads();
            if (g < 63) issueB(g + 1);   // overlaps this chunk's MMAs

            const uint32_t aBuf = sbase + OFF_A + c * 8192;
            const uint32_t bBuf = sbase + ((g & 1) ? OFF_B1 : OFF_B0);
#pragma unroll
            for (int ks = 0; ks < 4; ks++) {
                uint32_t afr[2][4];
#pragma unroll
                for (int mi = 0; mi < 2; mi++)
                    ldmatrix_x4(afr[mi][0], afr[mi][1], afr[mi][2], afr[mi][3],
                                aBuf + sw128((warpM * 32 + mi * 16 + laneRow) * 128 + ks * 32 + laneK * 16));
#pragma unroll
                for (int nq = 0; nq < 2; nq++) {
                    uint32_t r0, r1, r2, r3;
                    ldmatrix_x4(r0, r1, r2, r3,
                                bBuf + sw128((warpN * 32 + nq * 16 + laneRow) * 128 + ks * 32 + laneK * 16));
#pragma unroll
                    for (int mi = 0; mi < 2; mi++) {
                        mma_bf16(acc[mi][nq * 2],     afr[mi], r0, r2);
                        mma_bf16(acc[mi][nq * 2 + 1], afr[mi], r1, r3);
                    }
                }
            }
        }

        // ---- append: adj-only, two phases, 4-lane aggregated atomics ----
#pragma unroll 1
        for (int ph = 0; ph < 2; ph++) {
            if ((warpN >> 2) == ph) {
#pragma unroll
                for (int mi = 0; mi < 2; mi++) {
                    const int lr = lrBase + mi * 16;          // row A (lane>>2)
                    const int lr8 = lr + 8;                   // row B
                    const float th0 = thr[lr];
                    const float th1 = thr[lr8];

                    // pass counts per thread for its two rows
                    int c0 = 0, c1 = 0;
                    float s[4][4];
#pragma unroll
                    for (int n8 = 0; n8 < 4; n8++) {
#pragma unroll
                        for (int q = 0; q < 4; q++)
                            s[n8][q] = fmaxf(acc[mi][n8][q], 0.f);
                        c0 += (s[n8][0] > th0) + (s[n8][1] > th0);
                        c1 += (s[n8][2] > th1) + (s[n8][3] > th1);
                    }

                    // skip whole warp if nothing passes
                    if (__ballot_sync(0xffffffffu, (c0 | c1) != 0) == 0u) continue;

                    // inclusive prefix within 4-lane group (lanes share a row)
                    const int sub = lane & 3;
                    int p0 = c0, p1 = c1, v;
                    v = __shfl_up_sync(0xffffffffu, p0, 1); if (sub >= 1) p0 += v;
                    v = __shfl_up_sync(0xffffffffu, p0, 2); if (sub >= 2) p0 += v;
                    v = __shfl_up_sync(0xffffffffu, p1, 1); if (sub >= 1) p1 += v;
                    v = __shfl_up_sync(0xffffffffu, p1, 2); if (sub >= 2) p1 += v;
                    const int tot0 = __shfl_sync(0xffffffffu, p0, lane | 3);
                    const int tot1 = __shfl_sync(0xffffffffu, p1, lane | 3);

                    int base0 = 0, base1 = 0;
                    if (sub == 0) {
                        if (tot0 > 0) base0 = atomicAdd(&cnt[lr], tot0);
                        if (tot1 > 0) base1 = atomicAdd(&cnt[lr8], tot1);
                    }
                    base0 = __shfl_sync(0xffffffffu, base0, lane & ~3);
                    base1 = __shfl_sync(0xffffffffu, base1, lane & ~3);

                    int w0 = base0 + (p0 - c0);   // exclusive prefix
                    int w1 = base1 + (p1 - c1);
#pragma unroll
                    for (int n8 = 0; n8 < 4; n8++) {
                        const int col = colBase + warpN * 32 + n8 * 8 + sub * 2;
                        if (s[n8][0] > th0) {
                            if (w0 < CAP) { cs[lr * CAP + w0] = s[n8][0]; cj[lr * CAP + w0] = (uint16_t)col; }
                            w0++;
                        }
                        if (s[n8][1] > th0) {
                            if (w0 < CAP) { cs[lr * CAP + w0] = s[n8][1]; cj[lr * CAP + w0] = (uint16_t)(col + 1); }
                            w0++;
                        }
                        if (s[n8][2] > th1) {
                            if (w1 < CAP) { cs[lr8 * CAP + w1] = s[n8][2]; cj[lr8 * CAP + w1] = (uint16_t)col; }
                            w1++;
                        }
                        if (s[n8][3] > th1) {
                            if (w1 < CAP) { cs[lr8 * CAP + w1] = s[n8][3]; cj[lr8 * CAP + w1] = (uint16_t)(col + 1); }
                            w1++;
                        }
                    }
                }
            }
            __syncthreads();

            // ---- compaction: warp w owns rows w*4 .. w*4+3 ----
#pragma unroll 1
            for (int rr = 0; rr < 4; rr++) {
                const int r = warp * 4 + rr;
                int n = cnt[r];
                if (n > TRIGGER) {
                    if (n > CAP) n = CAP;
                    unsigned sbits[10];
#pragma unroll
                    for (int q = 0; q < 10; q++) {
                        int i = lane + q * 32;
                        sbits[q] = (i < n) ? __float_as_uint(cs[r * CAP + i]) : 0u;
                    }
                    unsigned lo = 0, hi = 0x7f800000u, T = 0;
                    for (int it = 0; it < 32; it++) {
                        unsigned mid = lo + ((hi - lo) >> 1);
                        int c = 0;
#pragma unroll
                        for (int q = 0; q < 10; q++)
                            c += __popc(__ballot_sync(0xffffffffu, sbits[q] > mid));
                        if (c > 96) lo = mid + 1;
                        else if (c < 48) { if (mid == 0) { T = 0; break; } hi = mid - 1; }
                        else { T = mid; break; }
                        if (lo > hi) { T = hi; break; }
                    }
                    // margin 0.035 = noise 0.01 + bf16 bound; zero-clamped
                    const float fT = fmaxf(__uint_as_float(T) - 0.035f, 1e-30f);
                    int base = 0;
#pragma unroll
                    for (int q = 0; q < 10; q++) {
                        int i = lane + q * 32;
                        bool keep = (i < n) && (__uint_as_float(sbits[q]) > fT);
                        unsigned m = __ballot_sync(0xffffffffu, keep);
                        float vv; uint16_t jv;
                        if (keep) { vv = cs[r * CAP + i]; jv = cj[r * CAP + i]; }
                        int pos = base + __popc(m & ((1u << lane) - 1u));
                        if (keep) { cs[r * CAP + pos] = vv; cj[r * CAP + pos] = jv; }
                        base += __popc(m);
                    }
                    if (lane == 0) { cnt[r] = base; thr[r] = fT; }
                }
                __syncwarp();
            }
            __syncthreads();
        }
    }

    // ------ tail: exact fp32 rescore + exact top-32 per row ------
    {
        float4* saf4 = (float4*)(smem + OFF_B0);   // 64 rows x 128 fp32 = 32KB
        for (int idx = tid; idx < 64 * 32; idx += 512) {
            int row = idx >> 5, k4 = idx & 31;
            saf4[idx] = *(const float4*)(g_Af + (size_t)(rowBase + row) * 128 + k4 * 4);
        }
    }
    __syncthreads();

    const float4* saf = (const float4*)(smem + OFF_B0);
    int* win = (int*)(smem + OFF_A) + warp * 64;

#pragma unroll 1
    for (int rr = 0; rr < 4; rr++) {
        const int r = warp * 4 + rr;
        const int rowG = rowBase + r;
        int n = cnt[r];
        if (n > CAP) n = CAP;

        for (int i = lane; i < n; i += 32) {
            const int j = (int)cj[r * CAP + i];
            float d = 0.f;
#pragma unroll
            for (int k4 = 0; k4 < 32; k4++) {
                float4 a = saf[r * 32 + k4];
                float4 b = *(const float4*)(g_Bf + (size_t)j * 128 + k4 * 4);
                d = fmaf(a.x, b.x, fmaf(a.y, b.y, fmaf(a.z, b.z, fmaf(a.w, b.w, d))));
            }
            float adjv = fmaxf(d, 0.f);
            float sc = __fadd_rn(adjv, __fmul_rn(0.01f, __ldg(noise + (size_t)rowG * N_NODES + j)));
            cs[r * CAP + i] = sc;
        }
        __syncwarp();

        unsigned sbits[10];
#pragma unroll
        for (int q = 0; q < 10; q++) {
            int i = lane + q * 32;
            sbits[q] = (i < n) ? __float_as_uint(cs[r * CAP + i]) : 0u;
        }
        unsigned lo = 0, hi = 0x7f800000u, T = 0;
        for (int it = 0; it < 32; it++) {
            unsigned mid = lo + ((hi - lo) >> 1);
            int c = 0;
#pragma unroll
            for (int q = 0; q < 10; q++)
                c += __popc(__ballot_sync(0xffffffffu, sbits[q] > mid));
            if (c > 48) lo = mid + 1;
            else if (c < 32) { if (mid == 0) { T = 0; break; } hi = mid - 1; }
            else { T = mid; break; }
            if (lo > hi) { T = hi; break; }
        }

        int wn = 0;
#pragma unroll
        for (int q = 0; q < 10; q++) {
            int i = lane + q * 32;
            bool keep = (i < n) && (sbits[q] > T);
            unsigned m = __ballot_sync(0xffffffffu, keep);
            int pos = wn + __popc(m & ((1u << lane) - 1u));
            if (keep && pos < 64) win[pos] = i;
            wn += __popc(m);
        }
        if (wn > 64) wn = 64;
        __syncwarp();

        while (wn > KSEL) {
            unsigned long long bk = ~0ull; int bp = -1;
            for (int p = lane; p < wn; p += 32) {
                int i = win[p];
                unsigned long long key =
                    ((unsigned long long)__float_as_uint(cs[r * CAP + i]) << 32)
                  | (unsigned)(0xFFFFu - cj[r * CAP + i]);
                if (key < bk) { bk = key; bp = p; }
            }
#pragma unroll
            for (int off = 16; off > 0; off >>= 1) {
                unsigned long long ok = __shfl_down_sync(0xffffffffu, bk, off);
                int op = __shfl_down_sync(0xffffffffu, bp, off);
                if (ok < bk) { bk = ok; bp = op; }
            }
            bp = __shfl_sync(0xffffffffu, bp, 0);
            if (lane == 0) win[bp] = win[wn - 1];
            __syncwarp();
            wn--;
        }

        if (lane < wn) {
            const int j = (int)cj[r * CAP + win[lane]];
            float d = 0.f;
#pragma unroll
            for (int k4 = 0; k4 < 32; k4++) {
                float4 a = saf[r * 32 + k4];
                float4 b = *(const float4*)(g_Bf + (size_t)j * 128 + k4 * 4);
                d = fmaf(a.x, b.x, fmaf(a.y, b.y, fmaf(a.z, b.z, fmaf(a.w, b.w, d))));
            }
            out[(size_t)rowG * N_NODES + j] = fmaxf(d, 0.f);
        }
        __syncwarp();
    }
}

// ---------------------------------------------------------------------------
extern "C" void kernel_launch(void* const* d_in, const int* in_sizes, int n_in,
                              void* d_out, int out_size)
{
    const float* emb   = (const float*)d_in[0];
    const float* noise = (const float*)d_in[1];
    const float* W1    = (const float*)d_in[2];
    const float* b1    = (const float*)d_in[3];
    const float* W2    = (const float*)d_in[4];
    const float* b2    = (const float*)d_in[5];
    float* out = (float*)d_out;

    cudaFuncSetAttribute(fused_kernel, cudaFuncAttributeMaxDynamicSharedMemorySize, SMEM_FUSED);

    prep_kernel<<<N_NODES / 16, 128>>>(emb, W1, b1, W2, b2);
    fused_kernel<<<N_NODES / ROWS_PER_CTA, 512, SMEM_FUSED>>>(noise, out);
}

// round 14
// speedup vs baseline: 1.1969x; 1.1969x over previous
#include <cuda_runtime.h>
#include <cuda_bf16.h>
#include <math.h>
#include <stdint.h>

#define N_NODES 8192
#define KSEL 32
#define ROWS_PER_CTA 64
#define CAP 256
#define TRIGGER 128

__device__ float g_Af[N_NODES * 128];                 // [v1 | -v2] fp32
__device__ float g_Bf[N_NODES * 128];                 // [v2 |  v1] fp32
__device__ __nv_bfloat16 g_Abf[N_NODES * 128];        // hi(A)
__device__ __nv_bfloat16 g_Bbf[N_NODES * 128];        // hi(B)

__device__ __forceinline__ uint32_t smem_u32(const void* p) {
    uint32_t a;
    asm("{ .reg .u64 t; cvta.to.shared.u64 t, %1; cvt.u32.u64 %0, t; }" : "=r"(a) : "l"(p));
    return a;
}
__device__ __forceinline__ uint32_t sw128(uint32_t byte) {
    return byte ^ ((byte >> 3) & 0x70);
}
__device__ __forceinline__ void ldmatrix_x4(uint32_t& r0, uint32_t& r1,
                                            uint32_t& r2, uint32_t& r3, uint32_t addr) {
    asm volatile("ldmatrix.sync.aligned.m8n8.x4.shared.b16 {%0,%1,%2,%3}, [%4];"
                 : "=r"(r0), "=r"(r1), "=r"(r2), "=r"(r3) : "r"(addr));
}
__device__ __forceinline__ void mma_bf16(float* c, const uint32_t* a, uint32_t b0, uint32_t b1) {
    asm volatile("mma.sync.aligned.m16n8k16.row.col.f32.bf16.bf16.f32 "
                 "{%0,%1,%2,%3}, {%4,%5,%6,%7}, {%8,%9}, {%0,%1,%2,%3};"
                 : "+f"(c[0]), "+f"(c[1]), "+f"(c[2]), "+f"(c[3])
                 : "r"(a[0]), "r"(a[1]), "r"(a[2]), "r"(a[3]), "r"(b0), "r"(b1));
}
__device__ __forceinline__ void cp_async16(uint32_t dst, const void* src) {
    asm volatile("cp.async.cg.shared.global [%0], [%1], 16;" :: "r"(dst), "l"(src) : "memory");
}
__device__ __forceinline__ void cp_commit() {
    asm volatile("cp.async.commit_group;" ::: "memory");
}
#define CP_WAIT(N) asm volatile("cp.async.wait_group %0;" :: "n"(N) : "memory")

// ---------------------------------------------------------------------------
// Kernel 0: zero the output (streaming stores at peak BW, out of fused kernel)
// ---------------------------------------------------------------------------
__global__ void __launch_bounds__(256) zero_kernel(float4* __restrict__ out4)
{
    const size_t i = (size_t)blockIdx.x * 256 + threadIdx.x;
    out4[i] = make_float4(0.f, 0.f, 0.f, 0.f);
}

// ---------------------------------------------------------------------------
// Kernel 1: prep — hi-only bf16 pack (unchanged)
// ---------------------------------------------------------------------------
__global__ void __launch_bounds__(128) prep_kernel(
    const float* __restrict__ emb,
    const float* __restrict__ W1, const float* __restrict__ b1,
    const float* __restrict__ W2, const float* __restrict__ b2)
{
    __shared__ float sW[2][64][65];
    __shared__ float sb[2][64];
    __shared__ float semb[16][64];

    const int tid = threadIdx.x;
    for (int i = tid; i < 64 * 64; i += 128) {
        int r = i >> 6, k = i & 63;
        sW[0][r][k] = W1[i];
        sW[1][r][k] = W2[i];
    }
    if (tid < 64) { sb[0][tid] = b1[tid]; sb[1][tid] = b2[tid]; }

    const int nodeBase = blockIdx.x * 16;
    for (int i = tid; i < 16 * 64; i += 128)
        semb[i >> 6][i & 63] = emb[(size_t)(nodeBase + (i >> 6)) * 64 + (i & 63)];
    __syncthreads();

    const int h = tid >> 6;
    const int r = tid & 63;
    for (int n = 0; n < 16; n++) {
        float acc = sb[h][r];
#pragma unroll
        for (int k = 0; k < 64; k++)
            acc = fmaf(semb[n][k], sW[h][r][k], acc);
        float v = 0.5f * acc * (1.0f + erff(acc * 0.70710678118654752f));
        const int node = nodeBase + n;

        if (h == 0) {
            g_Af[node * 128 + r]      = v;
            g_Bf[node * 128 + 64 + r] = v;
            __nv_bfloat16 hi = __float2bfloat16_rn(v);
            g_Abf[node * 128 + r]      = hi;
            g_Bbf[node * 128 + 64 + r] = hi;
        } else {
            float av = -v;
            g_Af[node * 128 + 64 + r] = av;
            g_Bf[node * 128 + r]      = v;
            g_Abf[node * 128 + 64 + r] = __float2bfloat16_rn(av);
            g_Bbf[node * 128 + r]      = __float2bfloat16_rn(v);
        }
    }
}

// ---------------------------------------------------------------------------
// Fused kernel: R10 geometry, cheap compaction (wide band [40,112],
// warm-start lo, dynamic ballot-word count), zero-fill removed.
// ---------------------------------------------------------------------------
#define OFF_A    0            // 2 chunks x 8KB = 16KB
#define OFF_B0   16384        // 32KB
#define OFF_B1   49152        // 32KB
#define OFF_CS   81920        // 64 * 256 * 4 = 65536
#define OFF_CJ   147456       // 64 * 256 * 2 = 32768
#define OFF_THR  180224
#define OFF_CNT  180480
#define SMEM_FUSED 180736

__global__ void __launch_bounds__(512) fused_kernel(
    const float* __restrict__ noise, float* __restrict__ out)
{
    extern __shared__ char smem[];
    const uint32_t sbase = smem_u32(smem);
    float*    cs  = (float*)(smem + OFF_CS);
    uint16_t* cj  = (uint16_t*)(smem + OFF_CJ);
    float*    thr = (float*)(smem + OFF_THR);
    int*      cnt = (int*)(smem + OFF_CNT);

    const int tid = threadIdx.x;
    const int lane = tid & 31;
    const int warp = tid >> 5;
    const int warpN = warp & 7;
    const int warpM = warp >> 3;
    const int rowBase = blockIdx.x * ROWS_PER_CTA;

    if (tid < 64) { thr[tid] = -1.0f; cnt[tid] = 0; }

    // load A strip: 64 rows x 256B, 2 chunks of 8KB, SW128
    {
        const char* gA = (const char*)g_Abf;
        for (int idx = tid; idx < 1024; idx += 512) {
            int row = idx >> 4, rem = idx & 15;
            int c = rem >> 3, q = rem & 7;
            uint4 v = *(const uint4*)(gA + (size_t)(rowBase + row) * 256 + c * 128 + q * 16);
            *(uint4*)(smem + OFF_A + c * 8192 + sw128(row * 128 + q * 16)) = v;
        }
    }

    const int laneRow = lane & 15;
    const int laneK = lane >> 4;
    const int rowB = tid >> 3;
    const int qB = tid & 7;
    uint32_t stB[4];
#pragma unroll
    for (int r = 0; r < 4; r++)
        stB[r] = sw128((rowB + r * 64) * 128 + qB * 16);

    const char* gB = (const char*)g_Bbf;
    const int lrBase = warpM * 32 + (lane >> 2);

    auto issueB = [&](int g) {
        const uint32_t dstBase = sbase + ((g & 1) ? OFF_B1 : OFF_B0);
        const int tt = g >> 1, cc = g & 1;
        const char* src = gB + (size_t)(tt * 256 + rowB) * 256 + cc * 128 + qB * 16;
#pragma unroll
        for (int r = 0; r < 4; r++)
            cp_async16(dstBase + stB[r], src + (size_t)r * 64 * 256);
        cp_commit();
    };

    issueB(0);

    for (int t = 0; t < 32; t++) {
        const int colBase = t * 256;

        float acc[2][4][4];
#pragma unroll
        for (int mi = 0; mi < 2; mi++)
#pragma unroll
            for (int n8 = 0; n8 < 4; n8++)
#pragma unroll
                for (int q = 0; q < 4; q++) acc[mi][n8][q] = 0.0f;

#pragma unroll
        for (int c = 0; c < 2; c++) {
            const int g = t * 2 + c;
            CP_WAIT(0);
            __syncthreads();
            if (g < 63) issueB(g + 1);   // overlaps this chunk's MMAs

            const uint32_t aBuf = sbase + OFF_A + c * 8192;
            const uint32_t bBuf = sbase + ((g & 1) ? OFF_B1 : OFF_B0);
#pragma unroll
            for (int ks = 0; ks < 4; ks++) {
                uint32_t afr[2][4];
#pragma unroll
                for (int mi = 0; mi < 2; mi++)
                    ldmatrix_x4(afr[mi][0], afr[mi][1], afr[mi][2], afr[mi][3],
                                aBuf + sw128((warpM * 32 + mi * 16 + laneRow) * 128 + ks * 32 + laneK * 16));
#pragma unroll
                for (int nq = 0; nq < 2; nq++) {
                    uint32_t r0, r1, r2, r3;
                    ldmatrix_x4(r0, r1, r2, r3,
                                bBuf + sw128((warpN * 32 + nq * 16 + laneRow) * 128 + ks * 32 + laneK * 16));
#pragma unroll
                    for (int mi = 0; mi < 2; mi++) {
                        mma_bf16(acc[mi][nq * 2],     afr[mi], r0, r2);
                        mma_bf16(acc[mi][nq * 2 + 1], afr[mi], r1, r3);
                    }
                }
            }
        }

        // ---- append: adj-only, two phases (R10 semantics) ----
#pragma unroll 1
        for (int ph = 0; ph < 2; ph++) {
            if ((warpN >> 2) == ph) {
#pragma unroll
                for (int mi = 0; mi < 2; mi++) {
                    const int lr = lrBase + mi * 16;
                    const float th0 = thr[lr];
                    const float th1 = thr[lr + 8];
#pragma unroll
                    for (int n8 = 0; n8 < 4; n8++) {
                        const int col = colBase + warpN * 32 + n8 * 8 + (lane & 3) * 2;
                        float s0 = fmaxf(acc[mi][n8][0], 0.f);
                        float s1 = fmaxf(acc[mi][n8][1], 0.f);
                        float s2 = fmaxf(acc[mi][n8][2], 0.f);
                        float s3 = fmaxf(acc[mi][n8][3], 0.f);
                        if (s0 > th0) {
                            int p = atomicAdd(&cnt[lr], 1);
                            if (p < CAP) { cs[lr * CAP + p] = s0; cj[lr * CAP + p] = (uint16_t)col; }
                        }
                        if (s1 > th0) {
                            int p = atomicAdd(&cnt[lr], 1);
                            if (p < CAP) { cs[lr * CAP + p] = s1; cj[lr * CAP + p] = (uint16_t)(col + 1); }
                        }
                        if (s2 > th1) {
                            int p = atomicAdd(&cnt[lr + 8], 1);
                            if (p < CAP) { cs[(lr + 8) * CAP + p] = s2; cj[(lr + 8) * CAP + p] = (uint16_t)col; }
                        }
                        if (s3 > th1) {
                            int p = atomicAdd(&cnt[lr + 8], 1);
                            if (p < CAP) { cs[(lr + 8) * CAP + p] = s3; cj[(lr + 8) * CAP + p] = (uint16_t)(col + 1); }
                        }
                    }
                }
            }
            __syncthreads();

            // ---- compaction: warp w owns rows w*4..w*4+3; CHEAP search ----
#pragma unroll 1
            for (int rr = 0; rr < 4; rr++) {
                const int r = warp * 4 + rr;
                int n = cnt[r];
                if (n > TRIGGER) {
                    if (n > CAP) n = CAP;
                    const int nw = (n + 31) >> 5;      // 5..8 ballot words
                    unsigned sbits[8];
#pragma unroll
                    for (int q = 0; q < 8; q++) {
                        int i = lane + q * 32;
                        sbits[q] = (i < n) ? __float_as_uint(cs[r * CAP + i]) : 0u;
                    }
                    // warm-start: new T >= previous threshold (monotone)
                    unsigned lo = __float_as_uint(fmaxf(thr[r], 0.0f));
                    unsigned hi = 0x7f800000u, T = 0;
                    for (int it = 0; it < 32; it++) {
                        unsigned mid = lo + ((hi - lo) >> 1);
                        int c = 0;
                        for (int q = 0; q < nw; q++)
                            c += __popc(__ballot_sync(0xffffffffu, sbits[q] > mid));
                        if (c > 112) lo = mid + 1;           // wide band [40,112]
                        else if (c < 40) { if (mid == 0) { T = 0; break; } hi = mid - 1; }
                        else { T = mid; break; }
                        if (lo > hi) { T = hi; break; }
                    }
                    // margin 0.035 = noise 0.01 + bf16 bound; zero-clamped
                    const float fT = fmaxf(__uint_as_float(T) - 0.035f, 1e-30f);
                    int base = 0;
                    for (int q = 0; q < nw; q++) {
                        int i = lane + q * 32;
                        bool keep = (i < n) && (__uint_as_float(sbits[q]) > fT);
                        unsigned m = __ballot_sync(0xffffffffu, keep);
                        float vv; uint16_t jv;
                        if (keep) { vv = cs[r * CAP + i]; jv = cj[r * CAP + i]; }
                        int pos = base + __popc(m & ((1u << lane) - 1u));
                        if (keep) { cs[r * CAP + pos] = vv; cj[r * CAP + pos] = jv; }
                        base += __popc(m);
                    }
                    if (lane == 0) { cnt[r] = base; thr[r] = fT; }
                }
                __syncwarp();
            }
            __syncthreads();
        }
    }

    // ------ tail: exact fp32 rescore + exact top-32 per row ------
    {
        float4* saf4 = (float4*)(smem + OFF_B0);   // 64 rows x 128 fp32 = 32KB
        for (int idx = tid; idx < 64 * 32; idx += 512) {
            int row = idx >> 5, k4 = idx & 31;
            saf4[idx] = *(const float4*)(g_Af + (size_t)(rowBase + row) * 128 + k4 * 4);
        }
    }
    __syncthreads();

    const float4* saf = (const float4*)(smem + OFF_B0);
    int* win = (int*)(smem + OFF_A) + warp * 64;

#pragma unroll 1
    for (int rr = 0; rr < 4; rr++) {
        const int r = warp * 4 + rr;
        const int rowG = rowBase + r;
        int n = cnt[r];
        if (n > CAP) n = CAP;

        for (int i = lane; i < n; i += 32) {
            const int j = (int)cj[r * CAP + i];
            float d = 0.f;
#pragma unroll
            for (int k4 = 0; k4 < 32; k4++) {
                float4 a = saf[r * 32 + k4];
                float4 b = *(const float4*)(g_Bf + (size_t)j * 128 + k4 * 4);
                d = fmaf(a.x, b.x, fmaf(a.y, b.y, fmaf(a.z, b.z, fmaf(a.w, b.w, d))));
            }
            float adjv = fmaxf(d, 0.f);
            float sc = __fadd_rn(adjv, __fmul_rn(0.01f, __ldg(noise + (size_t)rowG * N_NODES + j)));
            cs[r * CAP + i] = sc;
        }
        __syncwarp();

        unsigned sbits[8];
#pragma unroll
        for (int q = 0; q < 8; q++) {
            int i = lane + q * 32;
            sbits[q] = (i < n) ? __float_as_uint(cs[r * CAP + i]) : 0u;
        }
        unsigned lo = 0, hi = 0x7f800000u, T = 0;
        for (int it = 0; it < 32; it++) {
            unsigned mid = lo + ((hi - lo) >> 1);
            int c = 0;
#pragma unroll
            for (int q = 0; q < 8; q++)
                c += __popc(__ballot_sync(0xffffffffu, sbits[q] > mid));
            if (c > 48) lo = mid + 1;
            else if (c < 32) { if (mid == 0) { T = 0; break; } hi = mid - 1; }
            else { T = mid; break; }
            if (lo > hi) { T = hi; break; }
        }

        int wn = 0;
#pragma unroll
        for (int q = 0; q < 8; q++) {
            int i = lane + q * 32;
            bool keep = (i < n) && (sbits[q] > T);
            unsigned m = __ballot_sync(0xffffffffu, keep);
            int pos = wn + __popc(m & ((1u << lane) - 1u));
            if (keep && pos < 64) win[pos] = i;
            wn += __popc(m);
        }
        if (wn > 64) wn = 64;
        __syncwarp();

        while (wn > KSEL) {
            unsigned long long bk = ~0ull; int bp = -1;
            for (int p = lane; p < wn; p += 32) {
                int i = win[p];
                unsigned long long key =
                    ((unsigned long long)__float_as_uint(cs[r * CAP + i]) << 32)
                  | (unsigned)(0xFFFFu - cj[r * CAP + i]);
                if (key < bk) { bk = key; bp = p; }
            }
#pragma unroll
            for (int off = 16; off > 0; off >>= 1) {
                unsigned long long ok = __shfl_down_sync(0xffffffffu, bk, off);
                int op = __shfl_down_sync(0xffffffffu, bp, off);
                if (ok < bk) { bk = ok; bp = op; }
            }
            bp = __shfl_sync(0xffffffffu, bp, 0);
            if (lane == 0) win[bp] = win[wn - 1];
            __syncwarp();
            wn--;
        }

        if (lane < wn) {
            const int j = (int)cj[r * CAP + win[lane]];
            float d = 0.f;
#pragma unroll
            for (int k4 = 0; k4 < 32; k4++) {
                float4 a = saf[r * 32 + k4];
                float4 b = *(const float4*)(g_Bf + (size_t)j * 128 + k4 * 4);
                d = fmaf(a.x, b.x, fmaf(a.y, b.y, fmaf(a.z, b.z, fmaf(a.w, b.w, d))));
            }
            out[(size_t)rowG * N_NODES + j] = fmaxf(d, 0.f);
        }
        __syncwarp();
    }
}

// ---------------------------------------------------------------------------
extern "C" void kernel_launch(void* const* d_in, const int* in_sizes, int n_in,
                              void* d_out, int out_size)
{
    const float* emb   = (const float*)d_in[0];
    const float* noise = (const float*)d_in[1];
    const float* W1    = (const float*)d_in[2];
    const float* b1    = (const float*)d_in[3];
    const float* W2    = (const float*)d_in[4];
    const float* b2    = (const float*)d_in[5];
    float* out = (float*)d_out;

    cudaFuncSetAttribute(fused_kernel, cudaFuncAttributeMaxDynamicSharedMemorySize, SMEM_FUSED);

    // zero output at streaming-store peak (16.7M float4)
    zero_kernel<<<(N_NODES * (size_t)N_NODES / 4) / 256, 256>>>((float4*)out);
    prep_kernel<<<N_NODES / 16, 128>>>(emb, W1, b1, W2, b2);
    fused_kernel<<<N_NODES / ROWS_PER_CTA, 512, SMEM_FUSED>>>(noise, out);
}

// round 15
// speedup vs baseline: 1.4898x; 1.2447x over previous
#include <cuda_runtime.h>
#include <cuda_bf16.h>
#include <math.h>
#include <stdint.h>

#define N_NODES 8192
#define KSEL 32

__device__ float g_Af[N_NODES * 128];                 // [v1 | -v2] fp32
__device__ float g_Bf[N_NODES * 128];                 // [v2 |  v1] fp32
__device__ __nv_bfloat16 g_Abf[N_NODES * 128];        // hi(A)
__device__ __nv_bfloat16 g_Bbf[N_NODES * 128];        // hi(B)
__device__ __nv_bfloat16 g_S[(size_t)N_NODES * N_NODES];  // bf16 relu(adj_hat), 128MB

__device__ __forceinline__ uint32_t smem_u32(const void* p) {
    uint32_t a;
    asm("{ .reg .u64 t; cvta.to.shared.u64 t, %1; cvt.u32.u64 %0, t; }" : "=r"(a) : "l"(p));
    return a;
}
__device__ __forceinline__ uint32_t sw128(uint32_t byte) {
    return byte ^ ((byte >> 3) & 0x70);
}
__device__ __forceinline__ void ldmatrix_x4(uint32_t& r0, uint32_t& r1,
                                            uint32_t& r2, uint32_t& r3, uint32_t addr) {
    asm volatile("ldmatrix.sync.aligned.m8n8.x4.shared.b16 {%0,%1,%2,%3}, [%4];"
                 : "=r"(r0), "=r"(r1), "=r"(r2), "=r"(r3) : "r"(addr));
}
__device__ __forceinline__ void mma_bf16(float* c, const uint32_t* a, uint32_t b0, uint32_t b1) {
    asm volatile("mma.sync.aligned.m16n8k16.row.col.f32.bf16.bf16.f32 "
                 "{%0,%1,%2,%3}, {%4,%5,%6,%7}, {%8,%9}, {%0,%1,%2,%3};"
                 : "+f"(c[0]), "+f"(c[1]), "+f"(c[2]), "+f"(c[3])
                 : "r"(a[0]), "r"(a[1]), "r"(a[2]), "r"(a[3]), "r"(b0), "r"(b1));
}

// ---------------------------------------------------------------------------
// Kernel 1: prep — hi-only bf16 pack (unchanged, proven)
// ---------------------------------------------------------------------------
__global__ void __launch_bounds__(128) prep_kernel(
    const float* __restrict__ emb,
    const float* __restrict__ W1, const float* __restrict__ b1,
    const float* __restrict__ W2, const float* __restrict__ b2)
{
    __shared__ float sW[2][64][65];
    __shared__ float sb[2][64];
    __shared__ float semb[16][64];

    const int tid = threadIdx.x;
    for (int i = tid; i < 64 * 64; i += 128) {
        int r = i >> 6, k = i & 63;
        sW[0][r][k] = W1[i];
        sW[1][r][k] = W2[i];
    }
    if (tid < 64) { sb[0][tid] = b1[tid]; sb[1][tid] = b2[tid]; }

    const int nodeBase = blockIdx.x * 16;
    for (int i = tid; i < 16 * 64; i += 128)
        semb[i >> 6][i & 63] = emb[(size_t)(nodeBase + (i >> 6)) * 64 + (i & 63)];
    __syncthreads();

    const int h = tid >> 6;
    const int r = tid & 63;
    for (int n = 0; n < 16; n++) {
        float acc = sb[h][r];
#pragma unroll
        for (int k = 0; k < 64; k++)
            acc = fmaf(semb[n][k], sW[h][r][k], acc);
        float v = 0.5f * acc * (1.0f + erff(acc * 0.70710678118654752f));
        const int node = nodeBase + n;

        if (h == 0) {
            g_Af[node * 128 + r]      = v;
            g_Bf[node * 128 + 64 + r] = v;
            __nv_bfloat16 hi = __float2bfloat16_rn(v);
            g_Abf[node * 128 + r]      = hi;
            g_Bbf[node * 128 + 64 + r] = hi;
        } else {
            float av = -v;
            g_Af[node * 128 + 64 + r] = av;
            g_Bf[node * 128 + r]      = v;
            g_Abf[node * 128 + 64 + r] = __float2bfloat16_rn(av);
            g_Bbf[node * 128 + r]      = __float2bfloat16_rn(v);
        }
    }
}

// ---------------------------------------------------------------------------
// Kernel 2: pure GEMM — S = bf16(relu(A_hat @ B_hat^T)), 128x128 tiles, K=128
// (R3's passing gemm, K 384->128, bf16 epilogue; 2 barriers per CTA)
// ---------------------------------------------------------------------------
#define GOFF_A 0          // 2 chunks x 16KB
#define GOFF_B 32768      // 2 chunks x 16KB
#define GSMEM  65536

__global__ void __launch_bounds__(256) gemm_kernel()
{
    extern __shared__ char smem[];
    const uint32_t sbase = smem_u32(smem);
    const int tid = threadIdx.x;
    const int lane = tid & 31;
    const int warp = tid >> 5;
    const int warpM = warp & 3;          // 32-row slice
    const int warpN = warp >> 2;         // 64-col slice
    const int rowBase = blockIdx.y * 128;
    const int colBase = blockIdx.x * 128;

    // stage full A,B tiles (each 128 rows x 256B = 32KB as 2 chunks of 128B rows)
    {
        const char* gA = (const char*)g_Abf;
        const char* gB = (const char*)g_Bbf;
        for (int i = tid; i < 2048; i += 256) {
            int row = i >> 4, rem = i & 15;
            int c = rem >> 3, q = rem & 7;
            uint4 va = *(const uint4*)(gA + (size_t)(rowBase + row) * 256 + c * 128 + q * 16);
            *(uint4*)(smem + GOFF_A + c * 16384 + sw128(row * 128 + q * 16)) = va;
            uint4 vb = *(const uint4*)(gB + (size_t)(colBase + row) * 256 + c * 128 + q * 16);
            *(uint4*)(smem + GOFF_B + c * 16384 + sw128(row * 128 + q * 16)) = vb;
        }
    }
    __syncthreads();

    const int laneRow = lane & 15;
    const int laneK = lane >> 4;

    float acc[2][8][4];
#pragma unroll
    for (int mi = 0; mi < 2; mi++)
#pragma unroll
        for (int ng = 0; ng < 8; ng++)
#pragma unroll
            for (int q = 0; q < 4; q++) acc[mi][ng][q] = 0.0f;

#pragma unroll
    for (int ks = 0; ks < 8; ks++) {
        const int c = ks >> 2, kk = ks & 3;
        const uint32_t aBuf = sbase + GOFF_A + c * 16384;
        const uint32_t bBuf = sbase + GOFF_B + c * 16384;
        uint32_t afr[2][4];
#pragma unroll
        for (int mi = 0; mi < 2; mi++)
            ldmatrix_x4(afr[mi][0], afr[mi][1], afr[mi][2], afr[mi][3],
                        aBuf + sw128((warpM * 32 + mi * 16 + laneRow) * 128 + kk * 32 + laneK * 16));
#pragma unroll
        for (int nq = 0; nq < 4; nq++) {
            uint32_t r0, r1, r2, r3;
            ldmatrix_x4(r0, r1, r2, r3,
                        bBuf + sw128((warpN * 64 + nq * 16 + laneRow) * 128 + kk * 32 + laneK * 16));
#pragma unroll
            for (int mi = 0; mi < 2; mi++) {
                mma_bf16(acc[mi][nq * 2],     afr[mi], r0, r2);
                mma_bf16(acc[mi][nq * 2 + 1], afr[mi], r1, r3);
            }
        }
    }

    // epilogue: relu -> bf16x2 packed stores
    __nv_bfloat16* gS = g_S;
#pragma unroll
    for (int mi = 0; mi < 2; mi++) {
        const int r0 = rowBase + warpM * 32 + mi * 16 + (lane >> 2);
#pragma unroll
        for (int ng = 0; ng < 8; ng++) {
            const int col = colBase + warpN * 64 + ng * 8 + (lane & 3) * 2;
            __nv_bfloat162 p0 = __float22bfloat162_rn(
                make_float2(fmaxf(acc[mi][ng][0], 0.f), fmaxf(acc[mi][ng][1], 0.f)));
            *(uint32_t*)(gS + (size_t)r0 * N_NODES + col) = *(uint32_t*)&p0;
            __nv_bfloat162 p1 = __float22bfloat162_rn(
                make_float2(fmaxf(acc[mi][ng][2], 0.f), fmaxf(acc[mi][ng][3], 0.f)));
            *(uint32_t*)(gS + (size_t)(r0 + 8) * N_NODES + col) = *(uint32_t*)&p1;
        }
    }
}

// ---------------------------------------------------------------------------
// Kernel 3: per-row filter + exact rescore + exact top-32 + full-row write
// (R3's passing topk_kernel, re-sourced from bf16 S with margin band)
// ---------------------------------------------------------------------------
__global__ void __launch_bounds__(256) filter_kernel(
    const float* __restrict__ noise, float* __restrict__ out)
{
    const int row = blockIdx.x;
    const int tid = threadIdx.x;
    const int wid = tid >> 5, lane = tid & 31;
    const size_t base = (size_t)row * N_NODES;

    // load row of S: 32 u16 per thread (4 x uint4)
    uint16_t v[32];
    {
        const uint4* s4 = (const uint4*)(g_S + base);
#pragma unroll
        for (int k = 0; k < 4; k++) {
            uint4 u = s4[tid + k * 256];
            ((uint4*)v)[k] = u;
        }
    }

    __shared__ int wsum[8];
    __shared__ int sCnt;
    __shared__ alignas(16) float af[128];
    __shared__ uint16_t cand[512];
    __shared__ int nc;
    __shared__ unsigned long long keys[512];
    __shared__ float av[512];
    __shared__ int selj[KSEL];
    __shared__ float selv[KSEL];

    if (tid < 128) af[tid] = g_Af[(size_t)row * 128 + tid];
    if (tid == 0) nc = 0;

    // binary search on bf16 bits (u16, positive => bit order == value order):
    // count(v > T) in [40, 96]
    unsigned lo = 0, hi = 0x7F80u, T = 0;
    for (int it = 0; it < 18; it++) {
        unsigned mid = lo + ((hi - lo) >> 1);
        int c = 0;
#pragma unroll
        for (int e = 0; e < 32; e++) c += (v[e] > mid);
#pragma unroll
        for (int off = 16; off > 0; off >>= 1)
            c += __shfl_down_sync(0xffffffffu, c, off);
        if (lane == 0) wsum[wid] = c;
        __syncthreads();
        if (tid == 0) {
            int t = 0;
#pragma unroll
            for (int w = 0; w < 8; w++) t += wsum[w];
            sCnt = t;
        }
        __syncthreads();
        int cnt = sCnt;
        T = mid;
        if (cnt > 96)      lo = mid + 1;
        else if (cnt < 40) hi = mid;
        else break;
        if (lo >= hi) break;
        __syncthreads();
    }

    // gather candidates with margin 0.045 (noise 0.01 + bf16-mma 0.025 +
    // bf16-store 0.01), zero-clamped so relu zeros never enter (R6 lesson)
    const float Tf = fmaxf(__uint_as_float(T << 16) - 0.045f, 1e-30f);
#pragma unroll
    for (int e = 0; e < 32; e++) {
        float fv = __uint_as_float(((unsigned)v[e]) << 16);
        if (fv > Tf) {
            int p = atomicAdd(&nc, 1);
            if (p < 512) cand[p] = (uint16_t)((tid + (e >> 3) * 256) * 8 + (e & 7));
        }
    }
    __syncthreads();
    const int M = (nc < 512) ? nc : 512;

    // exact fp32 rescore: one candidate per warp (K=128 dot)
    for (int i = wid; i < M; i += 8) {
        const int j = (int)cand[i];
        const float4 b = *(const float4*)(g_Bf + (size_t)j * 128 + lane * 4);
        const float4 a = *(const float4*)(af + lane * 4);
        float p = fmaf(a.x, b.x, fmaf(a.y, b.y, fmaf(a.z, b.z, a.w * b.w)));
#pragma unroll
        for (int off = 16; off > 0; off >>= 1)
            p += __shfl_down_sync(0xffffffffu, p, off);
        if (lane == 0) {
            float adjv = fmaxf(p, 0.0f);
            float sc = __fadd_rn(adjv, __fmul_rn(0.01f, __ldg(noise + base + j)));
            keys[i] = ((unsigned long long)__float_as_uint(sc) << 32)
                    | (unsigned)(0xFFFFFFFFu - (unsigned)j);
            av[i] = adjv;
        }
    }
    __syncthreads();

    // exact top-32 (score desc, index asc) among candidates — warp 0
    if (wid == 0) {
        for (int r = 0; r < KSEL; r++) {
            unsigned long long bk = 0; int bi = -1;
            for (int i = lane; i < M; i += 32)
                if (keys[i] > bk) { bk = keys[i]; bi = i; }
#pragma unroll
            for (int off = 16; off > 0; off >>= 1) {
                unsigned long long ok = __shfl_down_sync(0xffffffffu, bk, off);
                int oi = __shfl_down_sync(0xffffffffu, bi, off);
                if (ok > bk) { bk = ok; bi = oi; }
            }
            if (lane == 0) {
                if (bi >= 0 && bk != 0ull) {
                    selj[r] = (int)cand[bi];
                    selv[r] = av[bi];
                    keys[bi] = 0ull;
                } else selj[r] = -1;
            }
            __syncwarp();
        }
    }
    __syncthreads();

    // write full row: zeros + scatter selected exact adj values
    const float4 z4 = make_float4(0.0f, 0.0f, 0.0f, 0.0f);
#pragma unroll
    for (int q = 0; q < 8; q++)
        ((float4*)(out + base))[tid + (q << 8)] = z4;
    __syncthreads();
    if (tid < KSEL) {
        int j = selj[tid];
        if (j >= 0) out[base + j] = selv[tid];
    }
}

// ---------------------------------------------------------------------------
extern "C" void kernel_launch(void* const* d_in, const int* in_sizes, int n_in,
                              void* d_out, int out_size)
{
    const float* emb   = (const float*)d_in[0];
    const float* noise = (const float*)d_in[1];
    const float* W1    = (const float*)d_in[2];
    const float* b1    = (const float*)d_in[3];
    const float* W2    = (const float*)d_in[4];
    const float* b2    = (const float*)d_in[5];
    float* out = (float*)d_out;

    cudaFuncSetAttribute(gemm_kernel, cudaFuncAttributeMaxDynamicSharedMemorySize, GSMEM);

    prep_kernel<<<N_NODES / 16, 128>>>(emb, W1, b1, W2, b2);

    dim3 g(N_NODES / 128, N_NODES / 128);
    gemm_kernel<<<g, 256, GSMEM>>>();

    filter_kernel<<<N_NODES, 256>>>(noise, out);
}

// round 16
// speedup vs baseline: 1.6502x; 1.1077x over previous
#include <cuda_runtime.h>
#include <cuda_bf16.h>
#include <math.h>
#include <stdint.h>

#define N_NODES 8192
#define KSEL 32

__device__ float g_Af[N_NODES * 128];                 // [v1 | -v2] fp32
__device__ float g_Bf[N_NODES * 128];                 // [v2 |  v1] fp32
__device__ __nv_bfloat16 g_Abf[N_NODES * 128];        // hi(A)
__device__ __nv_bfloat16 g_Bbf[N_NODES * 128];        // hi(B)
__device__ __nv_bfloat16 g_S[(size_t)N_NODES * N_NODES];  // bf16 relu(adj_hat)

__device__ __forceinline__ uint32_t smem_u32(const void* p) {
    uint32_t a;
    asm("{ .reg .u64 t; cvta.to.shared.u64 t, %1; cvt.u32.u64 %0, t; }" : "=r"(a) : "l"(p));
    return a;
}
__device__ __forceinline__ uint32_t sw128(uint32_t byte) {
    return byte ^ ((byte >> 3) & 0x70);
}
__device__ __forceinline__ void ldmatrix_x4(uint32_t& r0, uint32_t& r1,
                                            uint32_t& r2, uint32_t& r3, uint32_t addr) {
    asm volatile("ldmatrix.sync.aligned.m8n8.x4.shared.b16 {%0,%1,%2,%3}, [%4];"
                 : "=r"(r0), "=r"(r1), "=r"(r2), "=r"(r3) : "r"(addr));
}
__device__ __forceinline__ void mma_bf16(float* c, const uint32_t* a, uint32_t b0, uint32_t b1) {
    asm volatile("mma.sync.aligned.m16n8k16.row.col.f32.bf16.bf16.f32 "
                 "{%0,%1,%2,%3}, {%4,%5,%6,%7}, {%8,%9}, {%0,%1,%2,%3};"
                 : "+f"(c[0]), "+f"(c[1]), "+f"(c[2]), "+f"(c[3])
                 : "r"(a[0]), "r"(a[1]), "r"(a[2]), "r"(a[3]), "r"(b0), "r"(b1));
}
__device__ __forceinline__ void cp_async16(uint32_t dst, const void* src) {
    asm volatile("cp.async.cg.shared.global [%0], [%1], 16;" :: "r"(dst), "l"(src) : "memory");
}
__device__ __forceinline__ void cp_commit() {
    asm volatile("cp.async.commit_group;" ::: "memory");
}
#define CP_WAIT(N) asm volatile("cp.async.wait_group %0;" :: "n"(N) : "memory")

// ---------------------------------------------------------------------------
// Kernel 1: prep — hi-only bf16 pack (unchanged, proven)
// ---------------------------------------------------------------------------
__global__ void __launch_bounds__(128) prep_kernel(
    const float* __restrict__ emb,
    const float* __restrict__ W1, const float* __restrict__ b1,
    const float* __restrict__ W2, const float* __restrict__ b2)
{
    __shared__ float sW[2][64][65];
    __shared__ float sb[2][64];
    __shared__ float semb[16][64];

    const int tid = threadIdx.x;
    for (int i = tid; i < 64 * 64; i += 128) {
        int r = i >> 6, k = i & 63;
        sW[0][r][k] = W1[i];
        sW[1][r][k] = W2[i];
    }
    if (tid < 64) { sb[0][tid] = b1[tid]; sb[1][tid] = b2[tid]; }

    const int nodeBase = blockIdx.x * 16;
    for (int i = tid; i < 16 * 64; i += 128)
        semb[i >> 6][i & 63] = emb[(size_t)(nodeBase + (i >> 6)) * 64 + (i & 63)];
    __syncthreads();

    const int h = tid >> 6;
    const int r = tid & 63;
    for (int n = 0; n < 16; n++) {
        float acc = sb[h][r];
#pragma unroll
        for (int k = 0; k < 64; k++)
            acc = fmaf(semb[n][k], sW[h][r][k], acc);
        float v = 0.5f * acc * (1.0f + erff(acc * 0.70710678118654752f));
        const int node = nodeBase + n;

        if (h == 0) {
            g_Af[node * 128 + r]      = v;
            g_Bf[node * 128 + 64 + r] = v;
            __nv_bfloat16 hi = __float2bfloat16_rn(v);
            g_Abf[node * 128 + r]      = hi;
            g_Bbf[node * 128 + 64 + r] = hi;
        } else {
            float av = -v;
            g_Af[node * 128 + 64 + r] = av;
            g_Bf[node * 128 + r]      = v;
            g_Abf[node * 128 + 64 + r] = __float2bfloat16_rn(av);
            g_Bbf[node * 128 + r]      = __float2bfloat16_rn(v);
        }
    }
}

// ---------------------------------------------------------------------------
// Kernel 2: pure GEMM — S = bf16(relu(A_hat @ B_hat^T)), 128x128 tiles, K=128
// cp.async 2-chunk pipeline: chunk1 arrival overlaps chunk0 compute.
// ---------------------------------------------------------------------------
#define GOFF_A 0          // 2 chunks x 16KB
#define GOFF_B 32768      // 2 chunks x 16KB
#define GSMEM  65536

__global__ void __launch_bounds__(256) gemm_kernel()
{
    extern __shared__ char smem[];
    const uint32_t sbase = smem_u32(smem);
    const int tid = threadIdx.x;
    const int lane = tid & 31;
    const int warp = tid >> 5;
    const int warpM = warp & 3;          // 32-row slice
    const int warpN = warp >> 2;         // 64-col slice
    const int rowBase = blockIdx.y * 128;
    const int colBase = blockIdx.x * 128;

    const char* gA = (const char*)g_Abf;
    const char* gB = (const char*)g_Bbf;

    // stage chunk c via cp.async: A,B each 128 rows x 128B (1024 x 16B)
    auto stageChunk = [&](int c) {
#pragma unroll
        for (int j = 0; j < 4; j++) {
            int idx = tid + j * 256;
            int row = idx >> 3, q = idx & 7;
            cp_async16(sbase + GOFF_A + c * 16384 + sw128(row * 128 + q * 16),
                       gA + (size_t)(rowBase + row) * 256 + c * 128 + q * 16);
        }
#pragma unroll
        for (int j = 0; j < 4; j++) {
            int idx = tid + j * 256;
            int row = idx >> 3, q = idx & 7;
            cp_async16(sbase + GOFF_B + c * 16384 + sw128(row * 128 + q * 16),
                       gB + (size_t)(colBase + row) * 256 + c * 128 + q * 16);
        }
        cp_commit();
    };

    stageChunk(0);
    stageChunk(1);

    const int laneRow = lane & 15;
    const int laneK = lane >> 4;

    float acc[2][8][4];
#pragma unroll
    for (int mi = 0; mi < 2; mi++)
#pragma unroll
        for (int ng = 0; ng < 8; ng++)
#pragma unroll
            for (int q = 0; q < 4; q++) acc[mi][ng][q] = 0.0f;

#pragma unroll
    for (int c = 0; c < 2; c++) {
        if (c == 0) { CP_WAIT(1); } else { CP_WAIT(0); }
        __syncthreads();
        const uint32_t aBuf = sbase + GOFF_A + c * 16384;
        const uint32_t bBuf = sbase + GOFF_B + c * 16384;
#pragma unroll
        for (int kk = 0; kk < 4; kk++) {
            uint32_t afr[2][4];
#pragma unroll
            for (int mi = 0; mi < 2; mi++)
                ldmatrix_x4(afr[mi][0], afr[mi][1], afr[mi][2], afr[mi][3],
                            aBuf + sw128((warpM * 32 + mi * 16 + laneRow) * 128 + kk * 32 + laneK * 16));
#pragma unroll
            for (int nq = 0; nq < 4; nq++) {
                uint32_t r0, r1, r2, r3;
                ldmatrix_x4(r0, r1, r2, r3,
                            bBuf + sw128((warpN * 64 + nq * 16 + laneRow) * 128 + kk * 32 + laneK * 16));
#pragma unroll
                for (int mi = 0; mi < 2; mi++) {
                    mma_bf16(acc[mi][nq * 2],     afr[mi], r0, r2);
                    mma_bf16(acc[mi][nq * 2 + 1], afr[mi], r1, r3);
                }
            }
        }
    }

    // epilogue: relu -> bf16x2 packed stores
    __nv_bfloat16* gS = g_S;
#pragma unroll
    for (int mi = 0; mi < 2; mi++) {
        const int r0 = rowBase + warpM * 32 + mi * 16 + (lane >> 2);
#pragma unroll
        for (int ng = 0; ng < 8; ng++) {
            const int col = colBase + warpN * 64 + ng * 8 + (lane & 3) * 2;
            __nv_bfloat162 p0 = __float22bfloat162_rn(
                make_float2(fmaxf(acc[mi][ng][0], 0.f), fmaxf(acc[mi][ng][1], 0.f)));
            *(uint32_t*)(gS + (size_t)r0 * N_NODES + col) = *(uint32_t*)&p0;
            __nv_bfloat162 p1 = __float22bfloat162_rn(
                make_float2(fmaxf(acc[mi][ng][2], 0.f), fmaxf(acc[mi][ng][3], 0.f)));
            *(uint32_t*)(gS + (size_t)(r0 + 8) * N_NODES + col) = *(uint32_t*)&p1;
        }
    }
}

// ---------------------------------------------------------------------------
// Kernel 3: per-row filter + exact rescore (x2 ILP) + exact top-32 + row write
// ---------------------------------------------------------------------------
__global__ void __launch_bounds__(256) filter_kernel(
    const float* __restrict__ noise, float* __restrict__ out)
{
    const int row = blockIdx.x;
    const int tid = threadIdx.x;
    const int wid = tid >> 5, lane = tid & 31;
    const size_t base = (size_t)row * N_NODES;

    // load row of S: 32 u16 per thread (4 x uint4)
    uint16_t v[32];
    {
        const uint4* s4 = (const uint4*)(g_S + base);
#pragma unroll
        for (int k = 0; k < 4; k++) {
            uint4 u = s4[tid + k * 256];
            ((uint4*)v)[k] = u;
        }
    }

    __shared__ int wsum[8];
    __shared__ int sCnt;
    __shared__ alignas(16) float af[128];
    __shared__ uint16_t cand[512];
    __shared__ int nc;
    __shared__ unsigned long long keys[512];
    __shared__ float av[512];
    __shared__ int selj[KSEL];
    __shared__ float selv[KSEL];

    if (tid < 128) af[tid] = g_Af[(size_t)row * 128 + tid];
    if (tid == 0) nc = 0;

    // binary search on bf16 bits: count(v > T) in [40, 96]
    unsigned lo = 0, hi = 0x7F80u, T = 0;
    for (int it = 0; it < 18; it++) {
        unsigned mid = lo + ((hi - lo) >> 1);
        int c = 0;
#pragma unroll
        for (int e = 0; e < 32; e++) c += (v[e] > mid);
#pragma unroll
        for (int off = 16; off > 0; off >>= 1)
            c += __shfl_down_sync(0xffffffffu, c, off);
        if (lane == 0) wsum[wid] = c;
        __syncthreads();
        if (tid == 0) {
            int t = 0;
#pragma unroll
            for (int w = 0; w < 8; w++) t += wsum[w];
            sCnt = t;
        }
        __syncthreads();
        int cnt = sCnt;
        T = mid;
        if (cnt > 96)      lo = mid + 1;
        else if (cnt < 40) hi = mid;
        else break;
        if (lo >= hi) break;
        __syncthreads();
    }

    // gather candidates with margin 0.045, zero-clamped (R6 lesson)
    const float Tf = fmaxf(__uint_as_float(T << 16) - 0.045f, 1e-30f);
#pragma unroll
    for (int e = 0; e < 32; e++) {
        float fv = __uint_as_float(((unsigned)v[e]) << 16);
        if (fv > Tf) {
            int p = atomicAdd(&nc, 1);
            if (p < 512) cand[p] = (uint16_t)((tid + (e >> 3) * 256) * 8 + (e & 7));
        }
    }
    __syncthreads();
    const int M = (nc < 512) ? nc : 512;

    // exact fp32 rescore: TWO candidates per warp-iteration (hide L2 latency)
    {
        const float4 a = *(const float4*)(af + lane * 4);
        for (int i = wid; i < M; i += 16) {
            const int i1 = i + 8;
            const bool has1 = (i1 < M);
            const int j0 = (int)cand[i];
            const int j1 = has1 ? (int)cand[i1] : j0;
            const float4 b0 = *(const float4*)(g_Bf + (size_t)j0 * 128 + lane * 4);
            const float4 b1 = *(const float4*)(g_Bf + (size_t)j1 * 128 + lane * 4);
            float p0 = fmaf(a.x, b0.x, fmaf(a.y, b0.y, fmaf(a.z, b0.z, a.w * b0.w)));
            float p1 = fmaf(a.x, b1.x, fmaf(a.y, b1.y, fmaf(a.z, b1.z, a.w * b1.w)));
#pragma unroll
            for (int off = 16; off > 0; off >>= 1) {
                p0 += __shfl_down_sync(0xffffffffu, p0, off);
                p1 += __shfl_down_sync(0xffffffffu, p1, off);
            }
            if (lane == 0) {
                float adjv0 = fmaxf(p0, 0.0f);
                float sc0 = __fadd_rn(adjv0, __fmul_rn(0.01f, __ldg(noise + base + j0)));
                keys[i] = ((unsigned long long)__float_as_uint(sc0) << 32)
                        | (unsigned)(0xFFFFFFFFu - (unsigned)j0);
                av[i] = adjv0;
                if (has1) {
                    float adjv1 = fmaxf(p1, 0.0f);
                    float sc1 = __fadd_rn(adjv1, __fmul_rn(0.01f, __ldg(noise + base + j1)));
                    keys[i1] = ((unsigned long long)__float_as_uint(sc1) << 32)
                             | (unsigned)(0xFFFFFFFFu - (unsigned)j1);
                    av[i1] = adjv1;
                }
            }
        }
    }
    __syncthreads();

    // exact top-32 (score desc, index asc) among candidates — warp 0
    if (wid == 0) {
        for (int r = 0; r < KSEL; r++) {
            unsigned long long bk = 0; int bi = -1;
            for (int i = lane; i < M; i += 32)
                if (keys[i] > bk) { bk = keys[i]; bi = i; }
#pragma unroll
            for (int off = 16; off > 0; off >>= 1) {
                unsigned long long ok = __shfl_down_sync(0xffffffffu, bk, off);
                int oi = __shfl_down_sync(0xffffffffu, bi, off);
                if (ok > bk) { bk = ok; bi = oi; }
            }
            if (lane == 0) {
                if (bi >= 0 && bk != 0ull) {
                    selj[r] = (int)cand[bi];
                    selv[r] = av[bi];
                    keys[bi] = 0ull;
                } else selj[r] = -1;
            }
            __syncwarp();
        }
    }
    __syncthreads();

    // write full row: zeros + scatter selected exact adj values
    const float4 z4 = make_float4(0.0f, 0.0f, 0.0f, 0.0f);
#pragma unroll
    for (int q = 0; q < 8; q++)
        ((float4*)(out + base))[tid + (q << 8)] = z4;
    __syncthreads();
    if (tid < KSEL) {
        int j = selj[tid];
        if (j >= 0) out[base + j] = selv[tid];
    }
}

// ---------------------------------------------------------------------------
extern "C" void kernel_launch(void* const* d_in, const int* in_sizes, int n_in,
                              void* d_out, int out_size)
{
    const float* emb   = (const float*)d_in[0];
    const float* noise = (const float*)d_in[1];
    const float* W1    = (const float*)d_in[2];
    const float* b1    = (const float*)d_in[3];
    const float* W2    = (const float*)d_in[4];
    const float* b2    = (const float*)d_in[5];
    float* out = (float*)d_out;

    cudaFuncSetAttribute(gemm_kernel, cudaFuncAttributeMaxDynamicSharedMemorySize, GSMEM);

    prep_kernel<<<N_NODES / 16, 128>>>(emb, W1, b1, W2, b2);

    dim3 g(N_NODES / 128, N_NODES / 128);
    gemm_kernel<<<g, 256, GSMEM>>>();

    filter_kernel<<<N_NODES, 256>>>(noise, out);
}

// round 17
// speedup vs baseline: 2.0331x; 1.2321x over previous
#include <cuda_runtime.h>
#include <cuda_bf16.h>
#include <math.h>
#include <stdint.h>

#define N_NODES 8192
#define KSEL 32

__device__ float g_Af[N_NODES * 128];                 // [v1 | -v2] fp32
__device__ float g_Bf[N_NODES * 128];                 // [v2 |  v1] fp32
__device__ __nv_bfloat16 g_Abf[N_NODES * 128];        // hi(A)
__device__ __nv_bfloat16 g_Bbf[N_NODES * 128];        // hi(B)
__device__ __nv_bfloat16 g_S[(size_t)N_NODES * N_NODES];  // bf16 relu(adj_hat)

__device__ __forceinline__ uint32_t smem_u32(const void* p) {
    uint32_t a;
    asm("{ .reg .u64 t; cvta.to.shared.u64 t, %1; cvt.u32.u64 %0, t; }" : "=r"(a) : "l"(p));
    return a;
}
__device__ __forceinline__ uint32_t sw128(uint32_t byte) {
    return byte ^ ((byte >> 3) & 0x70);
}
__device__ __forceinline__ void ldmatrix_x4(uint32_t& r0, uint32_t& r1,
                                            uint32_t& r2, uint32_t& r3, uint32_t addr) {
    asm volatile("ldmatrix.sync.aligned.m8n8.x4.shared.b16 {%0,%1,%2,%3}, [%4];"
                 : "=r"(r0), "=r"(r1), "=r"(r2), "=r"(r3) : "r"(addr));
}
__device__ __forceinline__ void mma_bf16(float* c, const uint32_t* a, uint32_t b0, uint32_t b1) {
    asm volatile("mma.sync.aligned.m16n8k16.row.col.f32.bf16.bf16.f32 "
                 "{%0,%1,%2,%3}, {%4,%5,%6,%7}, {%8,%9}, {%0,%1,%2,%3};"
                 : "+f"(c[0]), "+f"(c[1]), "+f"(c[2]), "+f"(c[3])
                 : "r"(a[0]), "r"(a[1]), "r"(a[2]), "r"(a[3]), "r"(b0), "r"(b1));
}
__device__ __forceinline__ void cp_async16(uint32_t dst, const void* src) {
    asm volatile("cp.async.cg.shared.global [%0], [%1], 16;" :: "r"(dst), "l"(src) : "memory");
}
__device__ __forceinline__ void cp_commit() {
    asm volatile("cp.async.commit_group;" ::: "memory");
}
#define CP_WAIT(N) asm volatile("cp.async.wait_group %0;" :: "n"(N) : "memory")

// ---------------------------------------------------------------------------
// Kernel 1: prep — hi-only bf16 pack (unchanged, proven)
// ---------------------------------------------------------------------------
__global__ void __launch_bounds__(128) prep_kernel(
    const float* __restrict__ emb,
    const float* __restrict__ W1, const float* __restrict__ b1,
    const float* __restrict__ W2, const float* __restrict__ b2)
{
    __shared__ float sW[2][64][65];
    __shared__ float sb[2][64];
    __shared__ float semb[16][64];

    const int tid = threadIdx.x;
    for (int i = tid; i < 64 * 64; i += 128) {
        int r = i >> 6, k = i & 63;
        sW[0][r][k] = W1[i];
        sW[1][r][k] = W2[i];
    }
    if (tid < 64) { sb[0][tid] = b1[tid]; sb[1][tid] = b2[tid]; }

    const int nodeBase = blockIdx.x * 16;
    for (int i = tid; i < 16 * 64; i += 128)
        semb[i >> 6][i & 63] = emb[(size_t)(nodeBase + (i >> 6)) * 64 + (i & 63)];
    __syncthreads();

    const int h = tid >> 6;
    const int r = tid & 63;
    for (int n = 0; n < 16; n++) {
        float acc = sb[h][r];
#pragma unroll
        for (int k = 0; k < 64; k++)
            acc = fmaf(semb[n][k], sW[h][r][k], acc);
        float v = 0.5f * acc * (1.0f + erff(acc * 0.70710678118654752f));
        const int node = nodeBase + n;

        if (h == 0) {
            g_Af[node * 128 + r]      = v;
            g_Bf[node * 128 + 64 + r] = v;
            __nv_bfloat16 hi = __float2bfloat16_rn(v);
            g_Abf[node * 128 + r]      = hi;
            g_Bbf[node * 128 + 64 + r] = hi;
        } else {
            float av = -v;
            g_Af[node * 128 + 64 + r] = av;
            g_Bf[node * 128 + r]      = v;
            g_Abf[node * 128 + 64 + r] = __float2bfloat16_rn(av);
            g_Bbf[node * 128 + r]      = __float2bfloat16_rn(v);
        }
    }
}

// ---------------------------------------------------------------------------
// Kernel 2: triangular GEMM — upper-triangle tiles only (antisymmetry).
// Off-diagonal tiles also write the transposed block relu(-acc) via smem.
// ---------------------------------------------------------------------------
#define GOFF_A 0          // 2 chunks x 16KB
#define GOFF_B 32768      // 2 chunks x 16KB
#define GSMEM  65536
#define TSTRIDE 272       // transposed row stride: 128 bf16 (256B) + 16B pad

__global__ void __launch_bounds__(256) gemm_kernel()
{
    const int bi = blockIdx.y;           // row-tile
    const int bj = blockIdx.x;           // col-tile
    if (bj < bi) return;                 // lower triangle covered by transpose

    extern __shared__ char smem[];
    const uint32_t sbase = smem_u32(smem);
    const int tid = threadIdx.x;
    const int lane = tid & 31;
    const int warp = tid >> 5;
    const int warpM = warp & 3;          // 32-row slice
    const int warpN = warp >> 2;         // 64-col slice
    const int rowBase = bi * 128;
    const int colBase = bj * 128;

    const char* gA = (const char*)g_Abf;
    const char* gB = (const char*)g_Bbf;

    auto stageChunk = [&](int c) {
#pragma unroll
        for (int j = 0; j < 4; j++) {
            int idx = tid + j * 256;
            int row = idx >> 3, q = idx & 7;
            cp_async16(sbase + GOFF_A + c * 16384 + sw128(row * 128 + q * 16),
                       gA + (size_t)(rowBase + row) * 256 + c * 128 + q * 16);
        }
#pragma unroll
        for (int j = 0; j < 4; j++) {
            int idx = tid + j * 256;
            int row = idx >> 3, q = idx & 7;
            cp_async16(sbase + GOFF_B + c * 16384 + sw128(row * 128 + q * 16),
                       gB + (size_t)(colBase + row) * 256 + c * 128 + q * 16);
        }
        cp_commit();
    };

    stageChunk(0);
    stageChunk(1);

    const int laneRow = lane & 15;
    const int laneK = lane >> 4;

    float acc[2][8][4];
#pragma unroll
    for (int mi = 0; mi < 2; mi++)
#pragma unroll
        for (int ng = 0; ng < 8; ng++)
#pragma unroll
            for (int q = 0; q < 4; q++) acc[mi][ng][q] = 0.0f;

#pragma unroll
    for (int c = 0; c < 2; c++) {
        if (c == 0) { CP_WAIT(1); } else { CP_WAIT(0); }
        __syncthreads();
        const uint32_t aBuf = sbase + GOFF_A + c * 16384;
        const uint32_t bBuf = sbase + GOFF_B + c * 16384;
#pragma unroll
        for (int kk = 0; kk < 4; kk++) {
            uint32_t afr[2][4];
#pragma unroll
            for (int mi = 0; mi < 2; mi++)
                ldmatrix_x4(afr[mi][0], afr[mi][1], afr[mi][2], afr[mi][3],
                            aBuf + sw128((warpM * 32 + mi * 16 + laneRow) * 128 + kk * 32 + laneK * 16));
#pragma unroll
            for (int nq = 0; nq < 4; nq++) {
                uint32_t r0, r1, r2, r3;
                ldmatrix_x4(r0, r1, r2, r3,
                            bBuf + sw128((warpN * 64 + nq * 16 + laneRow) * 128 + kk * 32 + laneK * 16));
#pragma unroll
                for (int mi = 0; mi < 2; mi++) {
                    mma_bf16(acc[mi][nq * 2],     afr[mi], r0, r2);
                    mma_bf16(acc[mi][nq * 2 + 1], afr[mi], r1, r3);
                }
            }
        }
    }

    // direct epilogue: S[rowBase..][colBase..] = bf16(relu(acc))
    __nv_bfloat16* gS = g_S;
#pragma unroll
    for (int mi = 0; mi < 2; mi++) {
        const int r0 = rowBase + warpM * 32 + mi * 16 + (lane >> 2);
#pragma unroll
        for (int ng = 0; ng < 8; ng++) {
            const int col = colBase + warpN * 64 + ng * 8 + (lane & 3) * 2;
            __nv_bfloat162 p0 = __float22bfloat162_rn(
                make_float2(fmaxf(acc[mi][ng][0], 0.f), fmaxf(acc[mi][ng][1], 0.f)));
            *(uint32_t*)(gS + (size_t)r0 * N_NODES + col) = *(uint32_t*)&p0;
            __nv_bfloat162 p1 = __float22bfloat162_rn(
                make_float2(fmaxf(acc[mi][ng][2], 0.f), fmaxf(acc[mi][ng][3], 0.f)));
            *(uint32_t*)(gS + (size_t)(r0 + 8) * N_NODES + col) = *(uint32_t*)&p1;
        }
    }

    // transposed epilogue (off-diagonal only):
    // S[colBase + c][rowBase + r] = bf16(relu(-acc[r][c])), via smem transpose
    if (bj > bi) {
        __syncthreads();   // staging smem reads (ldmatrix) all done
        __nv_bfloat16* st = (__nv_bfloat16*)smem;   // [128 rows(c)] x TSTRIDE bytes
#pragma unroll
        for (int mi = 0; mi < 2; mi++) {
            const int r0 = warpM * 32 + mi * 16 + (lane >> 2);
#pragma unroll
            for (int ng = 0; ng < 8; ng++) {
                const int c0 = warpN * 64 + ng * 8 + (lane & 3) * 2;
                *(__nv_bfloat16*)((char*)st + c0 * TSTRIDE + r0 * 2) =
                    __float2bfloat16_rn(fmaxf(-acc[mi][ng][0], 0.f));
                *(__nv_bfloat16*)((char*)st + (c0 + 1) * TSTRIDE + r0 * 2) =
                    __float2bfloat16_rn(fmaxf(-acc[mi][ng][1], 0.f));
                *(__nv_bfloat16*)((char*)st + c0 * TSTRIDE + (r0 + 8) * 2) =
                    __float2bfloat16_rn(fmaxf(-acc[mi][ng][2], 0.f));
                *(__nv_bfloat16*)((char*)st + (c0 + 1) * TSTRIDE + (r0 + 8) * 2) =
                    __float2bfloat16_rn(fmaxf(-acc[mi][ng][3], 0.f));
            }
        }
        __syncthreads();
        // coalesced write: 128 rows x 256B = 2048 uint4, 8 per thread
#pragma unroll
        for (int j = 0; j < 8; j++) {
            int idx = tid + j * 256;
            int c = idx >> 4, q = idx & 15;
            uint4 v = *(const uint4*)((char*)st + c * TSTRIDE + q * 16);
            *(uint4*)(gS + (size_t)(colBase + c) * N_NODES + rowBase + q * 8) = v;
        }
    }
}

// ---------------------------------------------------------------------------
// Kernel 3: per-row filter + exact rescore (x2 ILP) + threshold top-32
// ---------------------------------------------------------------------------
__global__ void __launch_bounds__(256) filter_kernel(
    const float* __restrict__ noise, float* __restrict__ out)
{
    const int row = blockIdx.x;
    const int tid = threadIdx.x;
    const int wid = tid >> 5, lane = tid & 31;
    const size_t base = (size_t)row * N_NODES;

    uint16_t v[32];
    {
        const uint4* s4 = (const uint4*)(g_S + base);
#pragma unroll
        for (int k = 0; k < 4; k++) {
            uint4 u = s4[tid + k * 256];
            ((uint4*)v)[k] = u;
        }
    }

    __shared__ int wsum[8];
    __shared__ int sCnt;
    __shared__ alignas(16) float af[128];
    __shared__ uint16_t cand[512];
    __shared__ int nc;
    __shared__ unsigned long long keys[512];
    __shared__ float av[512];
    __shared__ int win[64];
    __shared__ int selj[KSEL];
    __shared__ float selv[KSEL];
    __shared__ int swn;

    if (tid < 128) af[tid] = g_Af[(size_t)row * 128 + tid];
    if (tid == 0) nc = 0;

    // binary search on bf16 bits: count(v > T) in [40, 96]
    unsigned lo = 0, hi = 0x7F80u, T = 0;
    for (int it = 0; it < 18; it++) {
        unsigned mid = lo + ((hi - lo) >> 1);
        int c = 0;
#pragma unroll
        for (int e = 0; e < 32; e++) c += (v[e] > mid);
#pragma unroll
        for (int off = 16; off > 0; off >>= 1)
            c += __shfl_down_sync(0xffffffffu, c, off);
        if (lane == 0) wsum[wid] = c;
        __syncthreads();
        if (tid == 0) {
            int t = 0;
#pragma unroll
            for (int w = 0; w < 8; w++) t += wsum[w];
            sCnt = t;
        }
        __syncthreads();
        int cnt = sCnt;
        T = mid;
        if (cnt > 96)      lo = mid + 1;
        else if (cnt < 40) hi = mid;
        else break;
        if (lo >= hi) break;
        __syncthreads();
    }

    // gather candidates with margin 0.045, zero-clamped (R6 lesson)
    const float Tf = fmaxf(__uint_as_float(T << 16) - 0.045f, 1e-30f);
#pragma unroll
    for (int e = 0; e < 32; e++) {
        float fv = __uint_as_float(((unsigned)v[e]) << 16);
        if (fv > Tf) {
            int p = atomicAdd(&nc, 1);
            if (p < 512) cand[p] = (uint16_t)((tid + (e >> 3) * 256) * 8 + (e & 7));
        }
    }
    __syncthreads();
    const int M = (nc < 512) ? nc : 512;

    // exact fp32 rescore: two candidates per warp-iteration
    {
        const float4 a = *(const float4*)(af + lane * 4);
        for (int i = wid; i < M; i += 16) {
            const int i1 = i + 8;
            const bool has1 = (i1 < M);
            const int j0 = (int)cand[i];
            const int j1 = has1 ? (int)cand[i1] : j0;
            const float4 b0 = *(const float4*)(g_Bf + (size_t)j0 * 128 + lane * 4);
            const float4 b1 = *(const float4*)(g_Bf + (size_t)j1 * 128 + lane * 4);
            float p0 = fmaf(a.x, b0.x, fmaf(a.y, b0.y, fmaf(a.z, b0.z, a.w * b0.w)));
            float p1 = fmaf(a.x, b1.x, fmaf(a.y, b1.y, fmaf(a.z, b1.z, a.w * b1.w)));
#pragma unroll
            for (int off = 16; off > 0; off >>= 1) {
                p0 += __shfl_down_sync(0xffffffffu, p0, off);
                p1 += __shfl_down_sync(0xffffffffu, p1, off);
            }
            if (lane == 0) {
                float adjv0 = fmaxf(p0, 0.0f);
                float sc0 = __fadd_rn(adjv0, __fmul_rn(0.01f, __ldg(noise + base + j0)));
                keys[i] = ((unsigned long long)__float_as_uint(sc0) << 32)
                        | (unsigned)(0xFFFFFFFFu - (unsigned)j0);
                av[i] = adjv0;
                if (has1) {
                    float adjv1 = fmaxf(p1, 0.0f);
                    float sc1 = __fadd_rn(adjv1, __fmul_rn(0.01f, __ldg(noise + base + j1)));
                    keys[i1] = ((unsigned long long)__float_as_uint(sc1) << 32)
                             | (unsigned)(0xFFFFFFFFu - (unsigned)j1);
                    av[i1] = adjv1;
                }
            }
        }
    }
    __syncthreads();

    // top-32: warp 0 binary-search score bits to [32,48], gather, trim to 32
    if (wid == 0) {
        const int nw = (M + 31) >> 5;
        unsigned lo2 = 0, hi2 = 0x7f800000u, T2 = 0;
        for (int it = 0; it < 32; it++) {
            unsigned mid = lo2 + ((hi2 - lo2) >> 1);
            int c = 0;
            for (int q = 0; q < nw; q++) {
                int i = lane + q * 32;
                unsigned sb = (i < M) ? (unsigned)(keys[i] >> 32) : 0u;
                c += __popc(__ballot_sync(0xffffffffu, sb > mid));
            }
            if (c > 48) lo2 = mid + 1;
            else if (c < 32) { if (mid == 0) { T2 = 0; break; } hi2 = mid - 1; }
            else { T2 = mid; break; }
            if (lo2 > hi2) { T2 = hi2; break; }
        }

        int wn = 0;
        for (int q = 0; q < nw; q++) {
            int i = lane + q * 32;
            unsigned sb = (i < M) ? (unsigned)(keys[i] >> 32) : 0u;
            bool keep = sb > T2;
            unsigned m = __ballot_sync(0xffffffffu, keep);
            int pos = wn + __popc(m & ((1u << lane) - 1u));
            if (keep && pos < 64) win[pos] = i;
            wn += __popc(m);
        }
        if (wn > 64) wn = 64;
        __syncwarp();

        while (wn > KSEL) {
            unsigned long long bk = ~0ull; int bp = -1;
            for (int p = lane; p < wn; p += 32) {
                unsigned long long k = keys[win[p]];
                if (k < bk) { bk = k; bp = p; }
            }
#pragma unroll
            for (int off = 16; off > 0; off >>= 1) {
                unsigned long long ok = __shfl_down_sync(0xffffffffu, bk, off);
                int op = __shfl_down_sync(0xffffffffu, bp, off);
                if (ok < bk) { bk = ok; bp = op; }
            }
            bp = __shfl_sync(0xffffffffu, bp, 0);
            if (lane == 0) win[bp] = win[wn - 1];
            __syncwarp();
            wn--;
        }
        if (lane == 0) swn = wn;
        __syncwarp();
        if (lane < wn) {
            int i = win[lane];
            selj[lane] = (int)cand[i];
            selv[lane] = av[i];
        }
    }
    __syncthreads();

    // write full row: zeros + scatter selected exact adj values
    const float4 z4 = make_float4(0.0f, 0.0f, 0.0f, 0.0f);
#pragma unroll
    for (int q = 0; q < 8; q++)
        ((float4*)(out + base))[tid + (q << 8)] = z4;
    __syncthreads();
    if (tid < swn) {
        out[base + selj[tid]] = selv[tid];
    }
}

// ---------------------------------------------------------------------------
extern "C" void kernel_launch(void* const* d_in, const int* in_sizes, int n_in,
                              void* d_out, int out_size)
{
    const float* emb   = (const float*)d_in[0];
    const float* noise = (const float*)d_in[1];
    const float* W1    = (const float*)d_in[2];
    const float* b1    = (const float*)d_in[3];
    const float* W2    = (const float*)d_in[4];
    const float* b2    = (const float*)d_in[5];
    float* out = (float*)d_out;

    cudaFuncSetAttribute(gemm_kernel, cudaFuncAttributeMaxDynamicSharedMemorySize, GSMEM);

    prep_kernel<<<N_NODES / 16, 128>>>(emb, W1, b1, W2, b2);

    dim3 g(N_NODES / 128, N_NODES / 128);
    gemm_kernel<<<g, 256, GSMEM>>>();

    filter_kernel<<<N_NODES, 256>>>(noise, out);
}